// round 14
// baseline (speedup 1.0000x reference)
#include <cuda_runtime.h>

#define NMAX 100000
#define EMAX 3200000

typedef unsigned long long u64;

// scratch (all __device__ globals; no allocation anywhere)
__device__ int    g_degi  [NMAX];
__device__ int    g_rowptr[NMAX + 1];
__device__ int    g_next  [NMAX];
__device__ int    g_bsum  [128];
__device__ int    g_ssrc  [EMAX];     // src ids sorted by dst (CSR adjacency)
__device__ float  g_dis   [NMAX];
__device__ float4 g_y     [NMAX * 4];
__device__ float4 g_y2    [NMAX * 4];
__device__ float4 g_A1    [NMAX * 4];
__device__ float4 g_B1    [NMAX * 4];
__device__ float4 g_A2    [NMAX * 4];
__device__ float4 g_B2    [NMAX * 4];

__device__ __forceinline__ float relu(float v) { return fmaxf(v, 0.0f); }

__device__ __forceinline__ u64 pack2(float lo, float hi) {
    u64 r; asm("mov.b64 %0, {%1, %2};" : "=l"(r) : "f"(lo), "f"(hi)); return r;
}
__device__ __forceinline__ u64 ffma2(u64 a, u64 b, u64 c) {
    u64 d; asm("fma.rn.f32x2 %0, %1, %2, %3;" : "=l"(d) : "l"(a), "l"(b), "l"(c)); return d;
}
__device__ __forceinline__ float2 unpack2(u64 v) {
    float2 f; asm("mov.b64 {%0, %1}, %2;" : "=f"(f.x), "=f"(f.y) : "l"(v)); return f;
}

// ---------------------------------------------------------------- degree
__global__ void k_deg(const int* __restrict__ ei, int E) {
    int e = blockIdx.x * blockDim.x + threadIdx.x;
    if (e < E) atomicAdd(&g_degi[ei[(size_t)E + e]], 1);
}

// -------------------------------------------- per-1024-chunk block sums
__global__ void k_bsum(int N) {
    int i = blockIdx.x * 1024 + threadIdx.x;
    int v = (i < N) ? g_degi[i] : 0;
#pragma unroll
    for (int o = 16; o; o >>= 1) v += __shfl_down_sync(0xFFFFFFFFu, v, o);
    __shared__ int ws[32];
    if ((threadIdx.x & 31) == 0) ws[threadIdx.x >> 5] = v;
    __syncthreads();
    if (threadIdx.x < 32) {
        int u = ws[threadIdx.x];
#pragma unroll
        for (int o = 16; o; o >>= 1) u += __shfl_down_sync(0xFFFFFFFFu, u, o);
        if (threadIdx.x == 0) g_bsum[blockIdx.x] = u;
    }
}

// ---------- rowptr: block base = reduce(bsum[0..bid)), then local scan
__global__ void k_rowptr2(int N, int E) {
    __shared__ int s[1024];
    __shared__ int ws[32];
    __shared__ int sbase;
    int t = threadIdx.x;

    int v = (t < blockIdx.x) ? g_bsum[t] : 0;
#pragma unroll
    for (int o = 16; o; o >>= 1) v += __shfl_down_sync(0xFFFFFFFFu, v, o);
    if ((t & 31) == 0) ws[t >> 5] = v;
    __syncthreads();
    if (t < 32) {
        int u = ws[t];
#pragma unroll
        for (int o = 16; o; o >>= 1) u += __shfl_down_sync(0xFFFFFFFFu, u, o);
        if (t == 0) sbase = u;
    }

    int i = blockIdx.x * 1024 + t;
    int d = (i < N) ? g_degi[i] : 0;
    s[t] = d;
    __syncthreads();
    for (int off = 1; off < 1024; off <<= 1) {
        int u = (t >= off) ? s[t - off] : 0;
        __syncthreads();
        s[t] += u;
        __syncthreads();
    }
    if (i < N) {
        int excl = sbase + s[t] - d;
        g_rowptr[i] = excl;
        g_next[i]   = excl;
    }
    if (blockIdx.x == 0 && t == 0) g_rowptr[N] = E;
}

// ------------------------------- scatter into CSR (bare src, 4B store)
__global__ void k_scatter(const int* __restrict__ ei, int E) {
    int e = blockIdx.x * blockDim.x + threadIdx.x;
    if (e >= E) return;
    int src = ei[e];
    int dst = ei[(size_t)E + e];
    int pos = atomicAdd(&g_next[dst], 1);
    g_ssrc[pos] = src;
}

// ------------------------------------------------- node precompute layer 1
__global__ void k_node1(const float* __restrict__ x,
                        const float* __restrict__ wn1, const float* __restrict__ bn1,
                        const float* __restrict__ we1, int N) {
    __shared__ float swn[48], sbn[16], sA[256], sB[256];
    for (int i = threadIdx.x; i < 48; i += blockDim.x) swn[i] = wn1[i];
    for (int i = threadIdx.x; i < 16; i += blockDim.x) sbn[i] = bn1[i];
    for (int i = threadIdx.x; i < 256; i += blockDim.x) {
        sA[i] = we1[i];
        sB[i] = we1[304 + i];
    }
    __syncthreads();
    int n = blockIdx.x * blockDim.x + threadIdx.x;
    if (n >= N) return;

    float x0 = x[(size_t)n*3], x1 = x[(size_t)n*3+1], x2 = x[(size_t)n*3+2];
    float dis = rsqrtf((float)g_degi[n]);
    g_dis[n] = dis;

    float h[16];
#pragma unroll
    for (int k = 0; k < 16; k++)
        h[k] = sbn[k] + x0*swn[k] + x1*swn[16+k] + x2*swn[32+k];

    float4* Y = &g_y[(size_t)n*4];
#pragma unroll
    for (int q = 0; q < 4; q++)
        Y[q] = make_float4(dis*h[4*q], dis*h[4*q+1], dis*h[4*q+2], dis*h[4*q+3]);

    float a[16], b[16];
#pragma unroll
    for (int k = 0; k < 16; k++) { a[k] = 0.f; b[k] = 0.f; }
#pragma unroll
    for (int j = 0; j < 16; j++)
#pragma unroll
        for (int k = 0; k < 16; k++) {
            a[k] += h[j] * sA[j*16+k];
            b[k] += h[j] * sB[j*16+k];
        }
    float4* A = &g_A1[(size_t)n*4];
    float4* B = &g_B1[(size_t)n*4];
#pragma unroll
    for (int q = 0; q < 4; q++) {
        A[q] = make_float4(a[4*q], a[4*q+1], a[4*q+2], a[4*q+3]);
        B[q] = make_float4(b[4*q], b[4*q+1], b[4*q+2], b[4*q+3]);
    }
}

// ---------- fused: quad CSR-gather (layer1) + PARALLEL node2 transform
__global__ void k_agg_node2(const float* __restrict__ wn2, const float* __restrict__ bn2,
                            const float* __restrict__ we2, int N) {
    __shared__ __align__(16) float sw[256];
    __shared__ __align__(16) float sA[256];
    __shared__ __align__(16) float sB[256];
    __shared__ float sbn[16];
    __shared__ float sagg[64 * 17];
    for (int i = threadIdx.x; i < 16; i += blockDim.x) sbn[i] = bn2[i];
    for (int i = threadIdx.x; i < 256; i += blockDim.x) {
        sw[i] = wn2[i];
        sA[i] = we2[i];
        sB[i] = we2[512 + i];
    }
    __syncthreads();

    int t = threadIdx.x;
    int lane = t & 3, q = t >> 2;
    int n = blockIdx.x * 64 + q;

    float4 acc = make_float4(0.f, 0.f, 0.f, 0.f);
    if (n < N) {
        int s  = g_rowptr[n];
        int en = g_rowptr[n + 1];
#pragma unroll 4
        for (int p = s; p < en; p++) {
            int src = g_ssrc[p];
            float4 v = g_y[(size_t)src * 4 + lane];
            acc.x += v.x; acc.y += v.y; acc.z += v.z; acc.w += v.w;
        }
    }
    float* sg = &sagg[q * 17 + lane * 4];
    sg[0] = acc.x; sg[1] = acc.y; sg[2] = acc.z; sg[3] = acc.w;
    __syncthreads();

    if (n >= N) return;
    float dis = g_dis[n];
    const float* ag = &sagg[q * 17];
    float h[16];
#pragma unroll
    for (int k = 0; k < 16; k++) h[k] = relu(dis * ag[k]);

    int kb = lane * 4;
    float4 bn = *(const float4*)&sbn[kb];
    float v0 = bn.x, v1 = bn.y, v2 = bn.z, v3 = bn.w;
    float a0 = 0.f, a1 = 0.f, a2 = 0.f, a3 = 0.f;
    float b0 = 0.f, b1 = 0.f, b2 = 0.f, b3 = 0.f;
#pragma unroll
    for (int j = 0; j < 16; j++) {
        float hj = h[j];
        float4 w = *(const float4*)&sw[j*16 + kb];
        v0 += hj*w.x; v1 += hj*w.y; v2 += hj*w.z; v3 += hj*w.w;
    }
    float vfull[16];
    {
        float mine[4] = {v0, v1, v2, v3};
#pragma unroll
        for (int srcl = 0; srcl < 4; srcl++) {
#pragma unroll
            for (int i = 0; i < 4; i++)
                vfull[srcl*4 + i] = __shfl_sync(0xFFFFFFFFu, mine[i], srcl, 4);
        }
    }
    g_y2[(size_t)n*4 + lane] = make_float4(dis*v0, dis*v1, dis*v2, dis*v3);

#pragma unroll
    for (int j = 0; j < 16; j++) {
        float vj = vfull[j];
        float4 wa = *(const float4*)&sA[j*16 + kb];
        float4 wb = *(const float4*)&sB[j*16 + kb];
        a0 += vj*wa.x; a1 += vj*wa.y; a2 += vj*wa.z; a3 += vj*wa.w;
        b0 += vj*wb.x; b1 += vj*wb.y; b2 += vj*wb.z; b3 += vj*wb.w;
    }
    g_A2[(size_t)n*4 + lane] = make_float4(a0, a1, a2, a3);
    g_B2[(size_t)n*4 + lane] = make_float4(b0, b1, b2, b3);
}

// ---------- fused: quad CSR-gather (layer2) + PARALLEL node output MLP
__global__ void k_agg_node3(const float* __restrict__ wnn1, const float* __restrict__ bnn1,
                            const float* __restrict__ wnn2, const float* __restrict__ bnn2,
                            float* __restrict__ out_node, int N) {
    __shared__ __align__(16) float sw1[256];
    __shared__ float sb1[16], sw2[48], sb2[3];
    __shared__ float sagg[64 * 17];
    for (int i = threadIdx.x; i < 256; i += blockDim.x) sw1[i] = wnn1[i];
    for (int i = threadIdx.x; i < 48;  i += blockDim.x) sw2[i] = wnn2[i];
    for (int i = threadIdx.x; i < 16;  i += blockDim.x) sb1[i] = bnn1[i];
    if (threadIdx.x < 3) sb2[threadIdx.x] = bnn2[threadIdx.x];
    __syncthreads();

    int t = threadIdx.x;
    int lane = t & 3, q = t >> 2;
    int n = blockIdx.x * 64 + q;

    float4 acc = make_float4(0.f, 0.f, 0.f, 0.f);
    if (n < N) {
        int s  = g_rowptr[n];
        int en = g_rowptr[n + 1];
#pragma unroll 4
        for (int p = s; p < en; p++) {
            int src = g_ssrc[p];
            float4 v = g_y2[(size_t)src * 4 + lane];
            acc.x += v.x; acc.y += v.y; acc.z += v.z; acc.w += v.w;
        }
    }
    float* sg = &sagg[q * 17 + lane * 4];
    sg[0] = acc.x; sg[1] = acc.y; sg[2] = acc.z; sg[3] = acc.w;
    __syncthreads();

    if (n >= N) return;
    float dis = g_dis[n];
    const float* ag = &sagg[q * 17];
    float h[16];
#pragma unroll
    for (int k = 0; k < 16; k++) h[k] = relu(dis * ag[k]);

    int kb = lane * 4;
    float4 bb = *(const float4*)&sb1[kb];
    float t0 = bb.x, t1 = bb.y, t2 = bb.z, t3 = bb.w;
#pragma unroll
    for (int j = 0; j < 16; j++) {
        float hj = h[j];
        float4 w = *(const float4*)&sw1[j*16 + kb];
        t0 += hj*w.x; t1 += hj*w.y; t2 += hj*w.z; t3 += hj*w.w;
    }
    float o0 = 0.f, o1 = 0.f, o2 = 0.f;
    float tl[4] = {t0, t1, t2, t3};
#pragma unroll
    for (int i = 0; i < 4; i++) {
        float tj = relu(tl[i]);
        int j = kb + i;
        o0 += tj * sw2[j*3    ];
        o1 += tj * sw2[j*3 + 1];
        o2 += tj * sw2[j*3 + 2];
    }
    o0 += __shfl_xor_sync(0xFFFFFFFFu, o0, 1, 4);
    o0 += __shfl_xor_sync(0xFFFFFFFFu, o0, 2, 4);
    o1 += __shfl_xor_sync(0xFFFFFFFFu, o1, 1, 4);
    o1 += __shfl_xor_sync(0xFFFFFFFFu, o1, 2, 4);
    o2 += __shfl_xor_sync(0xFFFFFFFFu, o2, 1, 4);
    o2 += __shfl_xor_sync(0xFFFFFFFFu, o2, 2, 4);

    if (lane < 3) {
        float val = (lane == 0) ? (o0 + sb2[0]) : (lane == 1) ? (o1 + sb2[1]) : (o2 + sb2[2]);
        out_node[(size_t)n*3 + lane] = val;
    }
}

// ------- layer-2 edge kernel, EID order, TWO edges per thread
// ei/ea/out all coalesced; A/B gathers random 64B.
__global__ void __launch_bounds__(256) k_edge2e(
                         const int* __restrict__ ei, const float* __restrict__ ea,
                         const float* __restrict__ we1, const float* __restrict__ be1,
                         const float* __restrict__ we2, const float* __restrict__ be2,
                         const float* __restrict__ wen1, const float* __restrict__ ben1,
                         const float* __restrict__ wen2, const float* __restrict__ ben2,
                         float* __restrict__ out_edge, int E) {
    __shared__ float sm1[48], sbe1[16], sbe2[16], sb1[16], sw2[48], sb2[3];
    __shared__ __align__(16) float sm2[256];
    __shared__ __align__(16) float sw1[256];
    for (int i = threadIdx.x; i < 48; i += blockDim.x) {
        sm1[i] = we1[256 + i];
        sw2[i] = wen2[i];
    }
    for (int i = threadIdx.x; i < 256; i += blockDim.x) {
        sm2[i] = we2[256 + i];
        sw1[i] = wen1[i];
    }
    for (int i = threadIdx.x; i < 16; i += blockDim.x) {
        sbe1[i] = be1[i]; sbe2[i] = be2[i]; sb1[i] = ben1[i];
    }
    if (threadIdx.x < 3) sb2[threadIdx.x] = ben2[threadIdx.x];
    __syncthreads();

    int base = blockIdx.x * 512;
    int e0 = base + threadIdx.x;
    int e1i = e0 + 256;
    bool v0 = e0 < E, v1 = e1i < E;
    int ec0 = v0 ? e0 : (E - 1);
    int ec1 = v1 ? e1i : (E - 1);

    int srcA = ei[ec0], dstA = ei[(size_t)E + ec0];   // coalesced
    int srcB = ei[ec1], dstB = ei[(size_t)E + ec1];   // coalesced

    float ea0a = ea[(size_t)ec0*3], ea1a = ea[(size_t)ec0*3+1], ea2a = ea[(size_t)ec0*3+2];
    float ea0b = ea[(size_t)ec1*3], ea1b = ea[(size_t)ec1*3+1], ea2b = ea[(size_t)ec1*3+2];

    float e1a[16], e1b[16];
    {
        const float4* Aa = &g_A1[(size_t)srcA*4];
        const float4* Ba = &g_B1[(size_t)dstA*4];
        const float4* Ab = &g_A1[(size_t)srcB*4];
        const float4* Bb = &g_B1[(size_t)dstB*4];
#pragma unroll
        for (int q = 0; q < 4; q++) {
            float4 ta = Aa[q], tb = Ba[q];
            float4 tc = Ab[q], td = Bb[q];
            int k = 4*q;
#pragma unroll
            for (int i = 0; i < 4; i++) {
                float wa = sm1[k+i], wb = sm1[16+k+i], wc = sm1[32+k+i], bbi = sbe1[k+i];
                float sa = (i==0?ta.x:i==1?ta.y:i==2?ta.z:ta.w) + (i==0?tb.x:i==1?tb.y:i==2?tb.z:tb.w);
                float sb = (i==0?tc.x:i==1?tc.y:i==2?tc.z:tc.w) + (i==0?td.x:i==1?td.y:i==2?td.z:td.w);
                e1a[k+i] = relu(sa + bbi + ea0a*wa + ea1a*wb + ea2a*wc);
                e1b[k+i] = relu(sb + bbi + ea0b*wa + ea1b*wb + ea2b*wc);
            }
        }
    }

    float e2a[16], e2b[16];
    {
        u64 acca[8], accb[8];
        const float4* Aa = &g_A2[(size_t)srcA*4];
        const float4* Ba = &g_B2[(size_t)dstA*4];
        const float4* Ab = &g_A2[(size_t)srcB*4];
        const float4* Bb = &g_B2[(size_t)dstB*4];
#pragma unroll
        for (int q = 0; q < 4; q++) {
            float4 ta = Aa[q], tb = Ba[q];
            float4 tc = Ab[q], td = Bb[q];
            acca[2*q  ] = pack2(ta.x + tb.x + sbe2[4*q  ], ta.y + tb.y + sbe2[4*q+1]);
            acca[2*q+1] = pack2(ta.z + tb.z + sbe2[4*q+2], ta.w + tb.w + sbe2[4*q+3]);
            accb[2*q  ] = pack2(tc.x + td.x + sbe2[4*q  ], tc.y + td.y + sbe2[4*q+1]);
            accb[2*q+1] = pack2(tc.z + td.z + sbe2[4*q+2], tc.w + td.w + sbe2[4*q+3]);
        }
        const u64* W = (const u64*)sm2;
#pragma unroll
        for (int j = 0; j < 16; j++) {
            u64 eja = pack2(e1a[j], e1a[j]);
            u64 ejb = pack2(e1b[j], e1b[j]);
#pragma unroll
            for (int kk = 0; kk < 8; kk++) {
                u64 w = W[j*8 + kk];
                acca[kk] = ffma2(eja, w, acca[kk]);
                accb[kk] = ffma2(ejb, w, accb[kk]);
            }
        }
#pragma unroll
        for (int kk = 0; kk < 8; kk++) {
            float2 fa = unpack2(acca[kk]);
            float2 fb = unpack2(accb[kk]);
            e2a[2*kk] = relu(fa.x); e2a[2*kk+1] = relu(fa.y);
            e2b[2*kk] = relu(fb.x); e2b[2*kk+1] = relu(fb.y);
        }
    }

    float tva[16], tvb[16];
    {
        u64 acca[8], accb[8];
#pragma unroll
        for (int kk = 0; kk < 8; kk++) {
            u64 b = pack2(sb1[2*kk], sb1[2*kk+1]);
            acca[kk] = b; accb[kk] = b;
        }
        const u64* W = (const u64*)sw1;
#pragma unroll
        for (int j = 0; j < 16; j++) {
            u64 eja = pack2(e2a[j], e2a[j]);
            u64 ejb = pack2(e2b[j], e2b[j]);
#pragma unroll
            for (int kk = 0; kk < 8; kk++) {
                u64 w = W[j*8 + kk];
                acca[kk] = ffma2(eja, w, acca[kk]);
                accb[kk] = ffma2(ejb, w, accb[kk]);
            }
        }
#pragma unroll
        for (int kk = 0; kk < 8; kk++) {
            float2 fa = unpack2(acca[kk]);
            float2 fb = unpack2(accb[kk]);
            tva[2*kk] = fa.x; tva[2*kk+1] = fa.y;
            tvb[2*kk] = fb.x; tvb[2*kk+1] = fb.y;
        }
    }

    float o0a = sb2[0], o1a = sb2[1], o2a = sb2[2];
    float o0b = sb2[0], o1b = sb2[1], o2b = sb2[2];
#pragma unroll
    for (int j = 0; j < 16; j++) {
        float w0 = sw2[j*3], w1 = sw2[j*3+1], w2 = sw2[j*3+2];
        float ta = relu(tva[j]);
        float tb = relu(tvb[j]);
        o0a += ta * w0; o1a += ta * w1; o2a += ta * w2;
        o0b += tb * w0; o1b += tb * w1; o2b += tb * w2;
    }
    if (v0) {
        out_edge[(size_t)e0*3    ] = o0a;   // coalesced
        out_edge[(size_t)e0*3 + 1] = o1a;
        out_edge[(size_t)e0*3 + 2] = o2a;
    }
    if (v1) {
        out_edge[(size_t)e1i*3    ] = o0b;  // coalesced
        out_edge[(size_t)e1i*3 + 1] = o1b;
        out_edge[(size_t)e1i*3 + 2] = o2b;
    }
}

extern "C" void kernel_launch(void* const* d_in, const int* in_sizes, int n_in,
                              void* d_out, int out_size) {
    const float* x    = (const float*)d_in[0];
    const float* ea   = (const float*)d_in[1];
    const int*   ei   = (const int*)d_in[2];      // int32 (JAX x64 disabled)
    const float *wn1 = (const float*)d_in[3],  *bn1 = (const float*)d_in[4];
    const float *we1 = (const float*)d_in[5],  *be1 = (const float*)d_in[6];
    const float *wn2 = (const float*)d_in[7],  *bn2 = (const float*)d_in[8];
    const float *we2 = (const float*)d_in[9],  *be2 = (const float*)d_in[10];
    const float *wnn1= (const float*)d_in[11], *bnn1= (const float*)d_in[12];
    const float *wnn2= (const float*)d_in[13], *bnn2= (const float*)d_in[14];
    const float *wen1= (const float*)d_in[15], *ben1= (const float*)d_in[16];
    const float *wen2= (const float*)d_in[17], *ben2= (const float*)d_in[18];

    int N = in_sizes[0] / 3;
    int E = in_sizes[1] / 3;
    float* out_node = (float*)d_out;
    float* out_edge = out_node + (size_t)N * 3;

    void* pdegi;
    cudaGetSymbolAddress(&pdegi, g_degi);

    const int TB = 256;
    int gbE   = (E + TB - 1) / TB;
    int gbE2  = (E + 511) / 512;
    int gbN   = (N + TB - 1) / TB;
    int gbN64 = (N + 63) / 64;
    int NB    = (N + 1023) / 1024;

    cudaStream_t s1;
    cudaStreamCreateWithFlags(&s1, cudaStreamNonBlocking);
    cudaEvent_t evDeg, evN1, evA2, evN3;
    cudaEventCreateWithFlags(&evDeg, cudaEventDisableTiming);
    cudaEventCreateWithFlags(&evN1,  cudaEventDisableTiming);
    cudaEventCreateWithFlags(&evA2,  cudaEventDisableTiming);
    cudaEventCreateWithFlags(&evN3,  cudaEventDisableTiming);

    cudaMemsetAsync(pdegi, 0, (size_t)N * sizeof(int));

    // main chain on default stream
    k_deg    <<<gbE,  TB>>>(ei, E);
    cudaEventRecord(evDeg, 0);
    k_bsum   <<<NB, 1024>>>(N);
    k_rowptr2<<<NB, 1024>>>(N, E);
    k_scatter<<<gbE,  TB>>>(ei, E);              // 4th kernel (profiled)

    // side stream: node1 overlaps with bsum/rowptr/scatter
    cudaStreamWaitEvent(s1, evDeg, 0);
    k_node1<<<gbN, TB, 0, s1>>>(x, wn1, bn1, we1, N);
    cudaEventRecord(evN1, s1);

    // join: agg_node2 needs scatter (main) + node1 (side)
    cudaStreamWaitEvent(0, evN1, 0);
    k_agg_node2<<<gbN64, TB>>>(wn2, bn2, we2, N);
    cudaEventRecord(evA2, 0);

    // fork: edge2e (main) || agg_node3 (side) — independent of each other
    cudaStreamWaitEvent(s1, evA2, 0);
    k_agg_node3<<<gbN64, TB, 0, s1>>>(wnn1, bnn1, wnn2, bnn2, out_node, N);
    cudaEventRecord(evN3, s1);

    k_edge2e<<<gbE2, TB>>>(ei, ea, we1, be1, we2, be2, wen1, ben1, wen2, ben2,
                           out_edge, E);

    // join back so the capture/launch ends on the default stream
    cudaStreamWaitEvent(0, evN3, 0);

    cudaEventDestroy(evDeg);
    cudaEventDestroy(evN1);
    cudaEventDestroy(evA2);
    cudaEventDestroy(evN3);
    cudaStreamDestroy(s1);
}

// round 15
// speedup vs baseline: 1.1490x; 1.1490x over previous
#include <cuda_runtime.h>

#define NMAX 100000
#define EMAX 3200000

typedef unsigned long long u64;

// scratch (all __device__ globals; no allocation anywhere)
__device__ int    g_degi  [NMAX];
__device__ int    g_rowptr[NMAX + 1];
__device__ int    g_next  [NMAX];
__device__ int    g_bsum  [128];
__device__ int4   g_sedge [EMAX];     // (src, eid, dst, 0) sorted by dst
__device__ float  g_dis   [NMAX];
__device__ float4 g_y     [NMAX * 4];
__device__ float4 g_y2    [NMAX * 4];
__device__ float4 g_A1    [NMAX * 4];
__device__ float4 g_B1    [NMAX * 4];
__device__ float4 g_A2    [NMAX * 4];
__device__ float4 g_B2    [NMAX * 4];

__device__ __forceinline__ float relu(float v) { return fmaxf(v, 0.0f); }

__device__ __forceinline__ u64 pack2(float lo, float hi) {
    u64 r; asm("mov.b64 %0, {%1, %2};" : "=l"(r) : "f"(lo), "f"(hi)); return r;
}
__device__ __forceinline__ u64 ffma2(u64 a, u64 b, u64 c) {
    u64 d; asm("fma.rn.f32x2 %0, %1, %2, %3;" : "=l"(d) : "l"(a), "l"(b), "l"(c)); return d;
}
__device__ __forceinline__ float2 unpack2(u64 v) {
    float2 f; asm("mov.b64 {%0, %1}, %2;" : "=f"(f.x), "=f"(f.y) : "l"(v)); return f;
}

// ---------------------------------------------------------------- degree
__global__ void k_deg(const int* __restrict__ ei, int E) {
    int e = blockIdx.x * blockDim.x + threadIdx.x;
    if (e < E) atomicAdd(&g_degi[ei[(size_t)E + e]], 1);
}

// -------------------------------------------- per-1024-chunk block sums
__global__ void k_bsum(int N) {
    int i = blockIdx.x * 1024 + threadIdx.x;
    int v = (i < N) ? g_degi[i] : 0;
#pragma unroll
    for (int o = 16; o; o >>= 1) v += __shfl_down_sync(0xFFFFFFFFu, v, o);
    __shared__ int ws[32];
    if ((threadIdx.x & 31) == 0) ws[threadIdx.x >> 5] = v;
    __syncthreads();
    if (threadIdx.x < 32) {
        int u = ws[threadIdx.x];
#pragma unroll
        for (int o = 16; o; o >>= 1) u += __shfl_down_sync(0xFFFFFFFFu, u, o);
        if (threadIdx.x == 0) g_bsum[blockIdx.x] = u;
    }
}

// ---------- rowptr: block base = reduce(bsum[0..bid)), then local scan
__global__ void k_rowptr2(int N, int E) {
    __shared__ int s[1024];
    __shared__ int ws[32];
    __shared__ int sbase;
    int t = threadIdx.x;

    int v = (t < blockIdx.x) ? g_bsum[t] : 0;
#pragma unroll
    for (int o = 16; o; o >>= 1) v += __shfl_down_sync(0xFFFFFFFFu, v, o);
    if ((t & 31) == 0) ws[t >> 5] = v;
    __syncthreads();
    if (t < 32) {
        int u = ws[t];
#pragma unroll
        for (int o = 16; o; o >>= 1) u += __shfl_down_sync(0xFFFFFFFFu, u, o);
        if (t == 0) sbase = u;
    }

    int i = blockIdx.x * 1024 + t;
    int d = (i < N) ? g_degi[i] : 0;
    s[t] = d;
    __syncthreads();
    for (int off = 1; off < 1024; off <<= 1) {
        int u = (t >= off) ? s[t - off] : 0;
        __syncthreads();
        s[t] += u;
        __syncthreads();
    }
    if (i < N) {
        int excl = sbase + s[t] - d;
        g_rowptr[i] = excl;
        g_next[i]   = excl;
    }
    if (blockIdx.x == 0 && t == 0) g_rowptr[N] = E;
}

// ----------------------------------------------------- scatter into CSR
__global__ void k_scatter(const int* __restrict__ ei, int E) {
    int e = blockIdx.x * blockDim.x + threadIdx.x;
    if (e >= E) return;
    int src = ei[e];
    int dst = ei[(size_t)E + e];
    int pos = atomicAdd(&g_next[dst], 1);
    g_sedge[pos] = make_int4(src, e, dst, 0);
}

// ------------------------------------------------- node precompute layer 1
__global__ void k_node1(const float* __restrict__ x,
                        const float* __restrict__ wn1, const float* __restrict__ bn1,
                        const float* __restrict__ we1, int N) {
    __shared__ float swn[48], sbn[16], sA[256], sB[256];
    for (int i = threadIdx.x; i < 48; i += blockDim.x) swn[i] = wn1[i];
    for (int i = threadIdx.x; i < 16; i += blockDim.x) sbn[i] = bn1[i];
    for (int i = threadIdx.x; i < 256; i += blockDim.x) {
        sA[i] = we1[i];
        sB[i] = we1[304 + i];
    }
    __syncthreads();
    int n = blockIdx.x * blockDim.x + threadIdx.x;
    if (n >= N) return;

    float x0 = x[(size_t)n*3], x1 = x[(size_t)n*3+1], x2 = x[(size_t)n*3+2];
    float dis = rsqrtf((float)g_degi[n]);
    g_dis[n] = dis;

    float h[16];
#pragma unroll
    for (int k = 0; k < 16; k++)
        h[k] = sbn[k] + x0*swn[k] + x1*swn[16+k] + x2*swn[32+k];

    float4* Y = &g_y[(size_t)n*4];
#pragma unroll
    for (int q = 0; q < 4; q++)
        Y[q] = make_float4(dis*h[4*q], dis*h[4*q+1], dis*h[4*q+2], dis*h[4*q+3]);

    float a[16], b[16];
#pragma unroll
    for (int k = 0; k < 16; k++) { a[k] = 0.f; b[k] = 0.f; }
#pragma unroll
    for (int j = 0; j < 16; j++)
#pragma unroll
        for (int k = 0; k < 16; k++) {
            a[k] += h[j] * sA[j*16+k];
            b[k] += h[j] * sB[j*16+k];
        }
    float4* A = &g_A1[(size_t)n*4];
    float4* B = &g_B1[(size_t)n*4];
#pragma unroll
    for (int q = 0; q < 4; q++) {
        A[q] = make_float4(a[4*q], a[4*q+1], a[4*q+2], a[4*q+3]);
        B[q] = make_float4(b[4*q], b[4*q+1], b[4*q+2], b[4*q+3]);
    }
}

// ---------- fused: quad CSR-gather (layer1) + PARALLEL node2 transform
__global__ void k_agg_node2(const float* __restrict__ wn2, const float* __restrict__ bn2,
                            const float* __restrict__ we2, int N) {
    __shared__ __align__(16) float sw[256];
    __shared__ __align__(16) float sA[256];
    __shared__ __align__(16) float sB[256];
    __shared__ float sbn[16];
    __shared__ float sagg[64 * 17];
    for (int i = threadIdx.x; i < 16; i += blockDim.x) sbn[i] = bn2[i];
    for (int i = threadIdx.x; i < 256; i += blockDim.x) {
        sw[i] = wn2[i];
        sA[i] = we2[i];
        sB[i] = we2[512 + i];
    }
    __syncthreads();

    int t = threadIdx.x;
    int lane = t & 3, q = t >> 2;
    int n = blockIdx.x * 64 + q;

    float4 acc = make_float4(0.f, 0.f, 0.f, 0.f);
    if (n < N) {
        int s  = g_rowptr[n];
        int en = g_rowptr[n + 1];
#pragma unroll 4
        for (int p = s; p < en; p++) {
            int src = g_sedge[p].x;
            float4 v = g_y[(size_t)src * 4 + lane];
            acc.x += v.x; acc.y += v.y; acc.z += v.z; acc.w += v.w;
        }
    }
    float* sg = &sagg[q * 17 + lane * 4];
    sg[0] = acc.x; sg[1] = acc.y; sg[2] = acc.z; sg[3] = acc.w;
    __syncthreads();

    if (n >= N) return;
    float dis = g_dis[n];
    const float* ag = &sagg[q * 17];
    float h[16];
#pragma unroll
    for (int k = 0; k < 16; k++) h[k] = relu(dis * ag[k]);

    int kb = lane * 4;
    float4 bn = *(const float4*)&sbn[kb];
    float v0 = bn.x, v1 = bn.y, v2 = bn.z, v3 = bn.w;
    float a0 = 0.f, a1 = 0.f, a2 = 0.f, a3 = 0.f;
    float b0 = 0.f, b1 = 0.f, b2 = 0.f, b3 = 0.f;
#pragma unroll
    for (int j = 0; j < 16; j++) {
        float hj = h[j];
        float4 w = *(const float4*)&sw[j*16 + kb];
        v0 += hj*w.x; v1 += hj*w.y; v2 += hj*w.z; v3 += hj*w.w;
    }
    float vfull[16];
    {
        float mine[4] = {v0, v1, v2, v3};
#pragma unroll
        for (int srcl = 0; srcl < 4; srcl++) {
#pragma unroll
            for (int i = 0; i < 4; i++)
                vfull[srcl*4 + i] = __shfl_sync(0xFFFFFFFFu, mine[i], srcl, 4);
        }
    }
    g_y2[(size_t)n*4 + lane] = make_float4(dis*v0, dis*v1, dis*v2, dis*v3);

#pragma unroll
    for (int j = 0; j < 16; j++) {
        float vj = vfull[j];
        float4 wa = *(const float4*)&sA[j*16 + kb];
        float4 wb = *(const float4*)&sB[j*16 + kb];
        a0 += vj*wa.x; a1 += vj*wa.y; a2 += vj*wa.z; a3 += vj*wa.w;
        b0 += vj*wb.x; b1 += vj*wb.y; b2 += vj*wb.z; b3 += vj*wb.w;
    }
    g_A2[(size_t)n*4 + lane] = make_float4(a0, a1, a2, a3);
    g_B2[(size_t)n*4 + lane] = make_float4(b0, b1, b2, b3);
}

// ---------- fused: quad CSR-gather (layer2) + PARALLEL node output MLP
__global__ void k_agg_node3(const float* __restrict__ wnn1, const float* __restrict__ bnn1,
                            const float* __restrict__ wnn2, const float* __restrict__ bnn2,
                            float* __restrict__ out_node, int N) {
    __shared__ __align__(16) float sw1[256];
    __shared__ float sb1[16], sw2[48], sb2[3];
    __shared__ float sagg[64 * 17];
    for (int i = threadIdx.x; i < 256; i += blockDim.x) sw1[i] = wnn1[i];
    for (int i = threadIdx.x; i < 48;  i += blockDim.x) sw2[i] = wnn2[i];
    for (int i = threadIdx.x; i < 16;  i += blockDim.x) sb1[i] = bnn1[i];
    if (threadIdx.x < 3) sb2[threadIdx.x] = bnn2[threadIdx.x];
    __syncthreads();

    int t = threadIdx.x;
    int lane = t & 3, q = t >> 2;
    int n = blockIdx.x * 64 + q;

    float4 acc = make_float4(0.f, 0.f, 0.f, 0.f);
    if (n < N) {
        int s  = g_rowptr[n];
        int en = g_rowptr[n + 1];
#pragma unroll 4
        for (int p = s; p < en; p++) {
            int src = g_sedge[p].x;
            float4 v = g_y2[(size_t)src * 4 + lane];
            acc.x += v.x; acc.y += v.y; acc.z += v.z; acc.w += v.w;
        }
    }
    float* sg = &sagg[q * 17 + lane * 4];
    sg[0] = acc.x; sg[1] = acc.y; sg[2] = acc.z; sg[3] = acc.w;
    __syncthreads();

    if (n >= N) return;
    float dis = g_dis[n];
    const float* ag = &sagg[q * 17];
    float h[16];
#pragma unroll
    for (int k = 0; k < 16; k++) h[k] = relu(dis * ag[k]);

    int kb = lane * 4;
    float4 bb = *(const float4*)&sb1[kb];
    float t0 = bb.x, t1 = bb.y, t2 = bb.z, t3 = bb.w;
#pragma unroll
    for (int j = 0; j < 16; j++) {
        float hj = h[j];
        float4 w = *(const float4*)&sw1[j*16 + kb];
        t0 += hj*w.x; t1 += hj*w.y; t2 += hj*w.z; t3 += hj*w.w;
    }
    float o0 = 0.f, o1 = 0.f, o2 = 0.f;
    float tl[4] = {t0, t1, t2, t3};
#pragma unroll
    for (int i = 0; i < 4; i++) {
        float tj = relu(tl[i]);
        int j = kb + i;
        o0 += tj * sw2[j*3    ];
        o1 += tj * sw2[j*3 + 1];
        o2 += tj * sw2[j*3 + 2];
    }
    o0 += __shfl_xor_sync(0xFFFFFFFFu, o0, 1, 4);
    o0 += __shfl_xor_sync(0xFFFFFFFFu, o0, 2, 4);
    o1 += __shfl_xor_sync(0xFFFFFFFFu, o1, 1, 4);
    o1 += __shfl_xor_sync(0xFFFFFFFFu, o1, 2, 4);
    o2 += __shfl_xor_sync(0xFFFFFFFFu, o2, 1, 4);
    o2 += __shfl_xor_sync(0xFFFFFFFFu, o2, 2, 4);

    if (lane < 3) {
        float val = (lane == 0) ? (o0 + sb2[0]) : (lane == 1) ? (o1 + sb2[1]) : (o2 + sb2[2]);
        out_node[(size_t)n*3 + lane] = val;
    }
}

// ------- layer-2 edge kernel, CSR order, THREE edges per thread
// (weight LDS loads amortized across 3 edges; block = 128 threads)
__global__ void __launch_bounds__(128) k_edge2c(
                         const float* __restrict__ ea,
                         const float* __restrict__ we1, const float* __restrict__ be1,
                         const float* __restrict__ we2, const float* __restrict__ be2,
                         const float* __restrict__ wen1, const float* __restrict__ ben1,
                         const float* __restrict__ wen2, const float* __restrict__ ben2,
                         float* __restrict__ out_edge, int E) {
    __shared__ float sm1[48], sbe1[16], sbe2[16], sb1[16], sw2[48], sb2[3];
    __shared__ __align__(16) float sm2[256];
    __shared__ __align__(16) float sw1[256];
    for (int i = threadIdx.x; i < 48; i += blockDim.x) {
        sm1[i] = we1[256 + i];
        sw2[i] = wen2[i];
    }
    for (int i = threadIdx.x; i < 256; i += blockDim.x) {
        sm2[i] = we2[256 + i];
        sw1[i] = wen1[i];
    }
    for (int i = threadIdx.x; i < 16; i += blockDim.x) {
        sbe1[i] = be1[i]; sbe2[i] = be2[i]; sb1[i] = ben1[i];
    }
    if (threadIdx.x < 3) sb2[threadIdx.x] = ben2[threadIdx.x];
    __syncthreads();

    int base = blockIdx.x * 384;
    int pp[3];
    bool vv[3];
    int4 rr[3];
#pragma unroll
    for (int m = 0; m < 3; m++) {
        pp[m] = base + m * 128 + threadIdx.x;
        vv[m] = pp[m] < E;
        rr[m] = vv[m] ? g_sedge[pp[m]] : make_int4(0, 0, 0, 0);
    }

    float eav[3][3];
#pragma unroll
    for (int m = 0; m < 3; m++) {
        size_t eb = (size_t)rr[m].y * 3;
        eav[m][0] = ea[eb]; eav[m][1] = ea[eb+1]; eav[m][2] = ea[eb+2];
    }

    // e1 for all 3 edges (shared sm1/sbe1 loads)
    float e1v[3][16];
    {
#pragma unroll
        for (int m = 0; m < 3; m++) {
            const float4* A = &g_A1[(size_t)rr[m].x*4];
            const float4* B = &g_B1[(size_t)rr[m].z*4];
#pragma unroll
            for (int q = 0; q < 4; q++) {
                float4 ta = A[q], tb = B[q];
                e1v[m][4*q  ] = ta.x + tb.x;
                e1v[m][4*q+1] = ta.y + tb.y;
                e1v[m][4*q+2] = ta.z + tb.z;
                e1v[m][4*q+3] = ta.w + tb.w;
            }
        }
#pragma unroll
        for (int k = 0; k < 16; k++) {
            float wa = sm1[k], wb = sm1[16+k], wc = sm1[32+k], bbi = sbe1[k];
#pragma unroll
            for (int m = 0; m < 3; m++)
                e1v[m][k] = relu(e1v[m][k] + bbi
                                 + eav[m][0]*wa + eav[m][1]*wb + eav[m][2]*wc);
        }
    }

    // e2 = relu(A2 + B2 + be2 + e1 @ sm2)   [f32x2, W shared across 3 edges]
    float e2v[3][16];
    {
        u64 acc[3][8];
#pragma unroll
        for (int m = 0; m < 3; m++) {
            const float4* A = &g_A2[(size_t)rr[m].x*4];
            const float4* B = &g_B2[(size_t)rr[m].z*4];
#pragma unroll
            for (int q = 0; q < 4; q++) {
                float4 ta = A[q], tb = B[q];
                acc[m][2*q  ] = pack2(ta.x + tb.x + sbe2[4*q  ], ta.y + tb.y + sbe2[4*q+1]);
                acc[m][2*q+1] = pack2(ta.z + tb.z + sbe2[4*q+2], ta.w + tb.w + sbe2[4*q+3]);
            }
        }
        const u64* W = (const u64*)sm2;
#pragma unroll
        for (int j = 0; j < 16; j++) {
            u64 ej0 = pack2(e1v[0][j], e1v[0][j]);
            u64 ej1 = pack2(e1v[1][j], e1v[1][j]);
            u64 ej2 = pack2(e1v[2][j], e1v[2][j]);
#pragma unroll
            for (int kk = 0; kk < 8; kk++) {
                u64 w = W[j*8 + kk];
                acc[0][kk] = ffma2(ej0, w, acc[0][kk]);
                acc[1][kk] = ffma2(ej1, w, acc[1][kk]);
                acc[2][kk] = ffma2(ej2, w, acc[2][kk]);
            }
        }
#pragma unroll
        for (int m = 0; m < 3; m++)
#pragma unroll
            for (int kk = 0; kk < 8; kk++) {
                float2 f = unpack2(acc[m][kk]);
                e2v[m][2*kk  ] = relu(f.x);
                e2v[m][2*kk+1] = relu(f.y);
            }
    }

    // t = e2 @ wen1 + b    [f32x2, W shared across 3 edges]
    float tvv[3][16];
    {
        u64 acc[3][8];
#pragma unroll
        for (int kk = 0; kk < 8; kk++) {
            u64 b = pack2(sb1[2*kk], sb1[2*kk+1]);
            acc[0][kk] = b; acc[1][kk] = b; acc[2][kk] = b;
        }
        const u64* W = (const u64*)sw1;
#pragma unroll
        for (int j = 0; j < 16; j++) {
            u64 ej0 = pack2(e2v[0][j], e2v[0][j]);
            u64 ej1 = pack2(e2v[1][j], e2v[1][j]);
            u64 ej2 = pack2(e2v[2][j], e2v[2][j]);
#pragma unroll
            for (int kk = 0; kk < 8; kk++) {
                u64 w = W[j*8 + kk];
                acc[0][kk] = ffma2(ej0, w, acc[0][kk]);
                acc[1][kk] = ffma2(ej1, w, acc[1][kk]);
                acc[2][kk] = ffma2(ej2, w, acc[2][kk]);
            }
        }
#pragma unroll
        for (int m = 0; m < 3; m++)
#pragma unroll
            for (int kk = 0; kk < 8; kk++) {
                float2 f = unpack2(acc[m][kk]);
                tvv[m][2*kk  ] = f.x;
                tvv[m][2*kk+1] = f.y;
            }
    }

    float oo[3][3];
#pragma unroll
    for (int m = 0; m < 3; m++) { oo[m][0] = sb2[0]; oo[m][1] = sb2[1]; oo[m][2] = sb2[2]; }
#pragma unroll
    for (int j = 0; j < 16; j++) {
        float w0 = sw2[j*3], w1 = sw2[j*3+1], w2 = sw2[j*3+2];
#pragma unroll
        for (int m = 0; m < 3; m++) {
            float tj = relu(tvv[m][j]);
            oo[m][0] += tj * w0; oo[m][1] += tj * w1; oo[m][2] += tj * w2;
        }
    }
#pragma unroll
    for (int m = 0; m < 3; m++) {
        if (vv[m]) {
            size_t ob = (size_t)rr[m].y * 3;
            out_edge[ob    ] = oo[m][0];
            out_edge[ob + 1] = oo[m][1];
            out_edge[ob + 2] = oo[m][2];
        }
    }
}

extern "C" void kernel_launch(void* const* d_in, const int* in_sizes, int n_in,
                              void* d_out, int out_size) {
    const float* x    = (const float*)d_in[0];
    const float* ea   = (const float*)d_in[1];
    const int*   ei   = (const int*)d_in[2];      // int32 (JAX x64 disabled)
    const float *wn1 = (const float*)d_in[3],  *bn1 = (const float*)d_in[4];
    const float *we1 = (const float*)d_in[5],  *be1 = (const float*)d_in[6];
    const float *wn2 = (const float*)d_in[7],  *bn2 = (const float*)d_in[8];
    const float *we2 = (const float*)d_in[9],  *be2 = (const float*)d_in[10];
    const float *wnn1= (const float*)d_in[11], *bnn1= (const float*)d_in[12];
    const float *wnn2= (const float*)d_in[13], *bnn2= (const float*)d_in[14];
    const float *wen1= (const float*)d_in[15], *ben1= (const float*)d_in[16];
    const float *wen2= (const float*)d_in[17], *ben2= (const float*)d_in[18];

    int N = in_sizes[0] / 3;
    int E = in_sizes[1] / 3;
    float* out_node = (float*)d_out;
    float* out_edge = out_node + (size_t)N * 3;

    void* pdegi;
    cudaGetSymbolAddress(&pdegi, g_degi);

    const int TB = 256;
    int gbE   = (E + TB - 1) / TB;
    int gbE3  = (E + 383) / 384;
    int gbN   = (N + TB - 1) / TB;
    int gbN64 = (N + 63) / 64;
    int NB    = (N + 1023) / 1024;

    cudaStream_t s1;
    cudaStreamCreateWithFlags(&s1, cudaStreamNonBlocking);
    cudaEvent_t evDeg, evN1, evA2, evN3;
    cudaEventCreateWithFlags(&evDeg, cudaEventDisableTiming);
    cudaEventCreateWithFlags(&evN1,  cudaEventDisableTiming);
    cudaEventCreateWithFlags(&evA2,  cudaEventDisableTiming);
    cudaEventCreateWithFlags(&evN3,  cudaEventDisableTiming);

    cudaMemsetAsync(pdegi, 0, (size_t)N * sizeof(int));

    // main chain on default stream
    k_deg    <<<gbE,  TB>>>(ei, E);
    cudaEventRecord(evDeg, 0);
    k_bsum   <<<NB, 1024>>>(N);
    k_rowptr2<<<NB, 1024>>>(N, E);
    k_scatter<<<gbE,  TB>>>(ei, E);              // 4th kernel (profiled)

    // side stream: node1 overlaps with bsum/rowptr/scatter
    cudaStreamWaitEvent(s1, evDeg, 0);
    k_node1<<<gbN, TB, 0, s1>>>(x, wn1, bn1, we1, N);
    cudaEventRecord(evN1, s1);

    // join: agg_node2 needs scatter (main) + node1 (side)
    cudaStreamWaitEvent(0, evN1, 0);
    k_agg_node2<<<gbN64, TB>>>(wn2, bn2, we2, N);
    cudaEventRecord(evA2, 0);

    // fork: edge2c (main) || agg_node3 (side) — independent of each other
    cudaStreamWaitEvent(s1, evA2, 0);
    k_agg_node3<<<gbN64, TB, 0, s1>>>(wnn1, bnn1, wnn2, bnn2, out_node, N);
    cudaEventRecord(evN3, s1);

    k_edge2c<<<gbE3, 128>>>(ea, we1, be1, we2, be2, wen1, ben1, wen2, ben2,
                            out_edge, E);

    // join back so the capture/launch ends on the default stream
    cudaStreamWaitEvent(0, evN3, 0);

    cudaEventDestroy(evDeg);
    cudaEventDestroy(evN1);
    cudaEventDestroy(evA2);
    cudaEventDestroy(evN3);
    cudaStreamDestroy(s1);
}